// round 1
// baseline (speedup 1.0000x reference)
#include <cuda_runtime.h>
#include <cstdint>

#define BB   16
#define LQ   256
#define LK   4096
#define EE   64
#define DD   32
#define LATD 32
#define HH   4
#define EKH  16

typedef unsigned long long ull;

// ---------------- scratch (device globals; no allocation allowed) ----------
__device__ __align__(16) float g_qproj[BB * LQ * EE];   // 1 MB
__device__ __align__(16) float g_kproj[BB * LK * EE];   // 16 MB
__device__ __align__(16) float g_w[BB * LK * 64];       // 16 MB : [m*v (32) | m (32)]

// ---------------- f32x2 packed-math helpers --------------------------------
__device__ __forceinline__ ull pack2(float lo, float hi) {
    ull r; asm("mov.b64 %0, {%1,%2};" : "=l"(r) : "f"(lo), "f"(hi)); return r;
}
__device__ __forceinline__ void unpack2(ull v, float& lo, float& hi) {
    asm("mov.b64 {%0,%1}, %2;" : "=f"(lo), "=f"(hi) : "l"(v));
}
__device__ __forceinline__ ull ffma2(ull a, ull b, ull c) {
    ull d; asm("fma.rn.f32x2 %0, %1, %2, %3;" : "=l"(d) : "l"(a), "l"(b), "l"(c));
    return d;
}

// ---------------- projection: out[row][e] = in[row][:] @ W + bias ----------
// W is (64 in, 64 out) row-major: W[j*64 + e]. One block = 64 rows.
__global__ void __launch_bounds__(256) proj_kernel(
    const float* __restrict__ in, const float* __restrict__ W,
    const float* __restrict__ bias, int which /*0=q,1=k*/)
{
    __shared__ __align__(16) float Wsh[64 * 64];
    __shared__ __align__(16) float Ish[64 * 68];

    float* out = which ? g_kproj : g_qproj;

    const int t = threadIdx.x;
    const long row0 = (long)blockIdx.x * 64;
    const float4* ing = (const float4*)(in + row0 * 64);
    #pragma unroll
    for (int i = t; i < 1024; i += 256) ((float4*)Wsh)[i] = ((const float4*)W)[i];
    #pragma unroll
    for (int i = t; i < 1024; i += 256) {
        int rr = i >> 4, c = i & 15;
        *(float4*)&Ish[rr * 68 + c * 4] = ing[i];
    }
    __syncthreads();

    const int e0 = (t & 15) * 4;
    const int rb = (t >> 4) * 4;
    float4 bv = *(const float4*)&bias[e0];
    float4 a0 = bv, a1 = bv, a2 = bv, a3 = bv;
    #pragma unroll 8
    for (int j = 0; j < 64; j++) {
        float4 wv = *(const float4*)&Wsh[j * 64 + e0];
        float i0 = Ish[(rb + 0) * 68 + j];
        float i1 = Ish[(rb + 1) * 68 + j];
        float i2 = Ish[(rb + 2) * 68 + j];
        float i3 = Ish[(rb + 3) * 68 + j];
        a0.x += i0 * wv.x; a0.y += i0 * wv.y; a0.z += i0 * wv.z; a0.w += i0 * wv.w;
        a1.x += i1 * wv.x; a1.y += i1 * wv.y; a1.z += i1 * wv.z; a1.w += i1 * wv.w;
        a2.x += i2 * wv.x; a2.y += i2 * wv.y; a2.z += i2 * wv.z; a2.w += i2 * wv.w;
        a3.x += i3 * wv.x; a3.y += i3 * wv.y; a3.z += i3 * wv.z; a3.w += i3 * wv.w;
    }
    *(float4*)&out[(row0 + rb + 0) * 64 + e0] = a0;
    *(float4*)&out[(row0 + rb + 1) * 64 + e0] = a1;
    *(float4*)&out[(row0 + rb + 2) * 64 + e0] = a2;
    *(float4*)&out[(row0 + rb + 3) * 64 + e0] = a3;
}

// ---------------- build W = [m*v | m] ---------------------------------------
__global__ void __launch_bounds__(256) wbuild_kernel(
    const float* __restrict__ v, const int* __restrict__ m)
{
    int i = blockIdx.x * 256 + threadIdx.x;   // over BB*LK*32
    if (i >= BB * LK * 32) return;
    int bk = i >> 5, d = i & 31;
    float mv = (float)m[i];
    g_w[bk * 64 + d]      = mv * v[i];
    g_w[bk * 64 + 32 + d] = mv;
}

// ---------------- main fused attention kernel -------------------------------
// grid (8 qtiles, 16 batches), 256 threads. Streams Lk in chunks of 64.
// Shared layout (floats):
//   Ks  [64*64]  @ 0       (reused as X [32*132] in epilogue, spills into Ws)
//   Ws  [64*64]  @ 4096
//   Es  [4*64*36]@ 8192    (reused as O [4*32*64] in epilogue)
//   Wos [128*32] @ 17408
//   bos [32]     @ 21504
#define SM_KS  0
#define SM_WS  4096
#define SM_ES  8192
#define SM_WOS 17408
#define SM_BOS 21504
#define SM_FLOATS 21536   // 86144 bytes

__global__ void __launch_bounds__(256) attn_main_kernel(
    const float* __restrict__ Wo, const float* __restrict__ bo,
    float* __restrict__ out)
{
    extern __shared__ __align__(16) float sh[];
    float* Ks  = sh + SM_KS;
    float* Ws  = sh + SM_WS;
    float* Es  = sh + SM_ES;
    float* Wos = sh + SM_WOS;
    float* bos = sh + SM_BOS;

    const int t = threadIdx.x;
    const int lane = t & 31;
    const int w = t >> 5;
    const int b = blockIdx.y;
    const int q0 = blockIdx.x * 32;

    // load Wo / bo once
    #pragma unroll
    for (int i = t; i < 1024; i += 256) ((float4*)Wos)[i] = ((const float4*)Wo)[i];
    if (t < 32) bos[t] = bo[t];

    // ---- phase-1 identity: warp w -> head h1, kk-half; lane = q within tile
    const int h1  = w & 3;
    const int kk0 = (w >> 2) * 32;
    ull qp[8];
    {
        const ulonglong2* qv =
            (const ulonglong2*)(g_qproj + ((long)(b * LQ + q0 + lane)) * EE + h1 * EKH);
        #pragma unroll
        for (int i = 0; i < 4; i++) { ulonglong2 v = qv[i]; qp[2*i] = v.x; qp[2*i+1] = v.y; }
    }

    // ---- phase-2 identity: h2, 4 q rows, 8 d columns (4 f32x2 pairs)
    const int h2 = t >> 6;
    const int r  = t & 63;
    const int q2 = (r >> 3) * 4;
    const int d0 = (r & 7) * 8;
    ull acc[4][4];
    #pragma unroll
    for (int i = 0; i < 4; i++)
        #pragma unroll
        for (int j = 0; j < 4; j++) acc[i][j] = 0ull;

    const float* kbase = g_kproj + (long)b * LK * EE;
    const float* wbase = g_w     + (long)b * LK * 64;
    const float* ebase = Es + h2 * 64 * 36 + q2;
    const float* wsd   = Ws + d0;
    const float* krow  = Ks + h1 * EKH;

    for (int c = 0; c < 64; ++c) {
        __syncthreads();   // previous phase-2 done with Ws/Es
        const float4* kg = (const float4*)(kbase + c * 64 * 64);
        const float4* wg = (const float4*)(wbase + c * 64 * 64);
        #pragma unroll
        for (int i = t; i < 1024; i += 256) {
            ((float4*)Ks)[i] = kg[i];
            ((float4*)Ws)[i] = wg[i];
        }
        __syncthreads();

        // phase 1: e = exp(q.k / 4); K reads warp-uniform (broadcast)
        #pragma unroll 2
        for (int i = 0; i < 32; i++) {
            int kk = kk0 + i;
            const ulonglong2* kv = (const ulonglong2*)(krow + kk * 64);
            ulonglong2 v0 = kv[0], v1 = kv[1], v2 = kv[2], v3 = kv[3];
            ull a0 = ffma2(qp[0], v0.x, 0ull);
            ull a1 = ffma2(qp[1], v0.y, 0ull);
            a0 = ffma2(qp[2], v1.x, a0);  a1 = ffma2(qp[3], v1.y, a1);
            a0 = ffma2(qp[4], v2.x, a0);  a1 = ffma2(qp[5], v2.y, a1);
            a0 = ffma2(qp[6], v3.x, a0);  a1 = ffma2(qp[7], v3.y, a1);
            float s0, s1, s2, s3; unpack2(a0, s0, s1); unpack2(a1, s2, s3);
            float s = (s0 + s2) + (s1 + s3);
            Es[(h1 * 64 + kk) * 36 + lane] = __expf(s * 0.25f);
        }
        __syncthreads();

        // phase 2: acc[q][d-pair] += e[q] * W[kk][d]
        #pragma unroll 4
        for (int kk = 0; kk < 64; kk++) {
            float4 ev = *(const float4*)(ebase + kk * 36);
            ulonglong2 u0 = *(const ulonglong2*)(wsd + kk * 64);
            ulonglong2 u1 = *(const ulonglong2*)(wsd + kk * 64 + 4);
            ull ee0 = pack2(ev.x, ev.x), ee1 = pack2(ev.y, ev.y);
            ull ee2 = pack2(ev.z, ev.z), ee3 = pack2(ev.w, ev.w);
            acc[0][0] = ffma2(ee0, u0.x, acc[0][0]);
            acc[0][1] = ffma2(ee0, u0.y, acc[0][1]);
            acc[0][2] = ffma2(ee0, u1.x, acc[0][2]);
            acc[0][3] = ffma2(ee0, u1.y, acc[0][3]);
            acc[1][0] = ffma2(ee1, u0.x, acc[1][0]);
            acc[1][1] = ffma2(ee1, u0.y, acc[1][1]);
            acc[1][2] = ffma2(ee1, u1.x, acc[1][2]);
            acc[1][3] = ffma2(ee1, u1.y, acc[1][3]);
            acc[2][0] = ffma2(ee2, u0.x, acc[2][0]);
            acc[2][1] = ffma2(ee2, u0.y, acc[2][1]);
            acc[2][2] = ffma2(ee2, u1.x, acc[2][2]);
            acc[2][3] = ffma2(ee2, u1.y, acc[2][3]);
            acc[3][0] = ffma2(ee3, u0.x, acc[3][0]);
            acc[3][1] = ffma2(ee3, u0.y, acc[3][1]);
            acc[3][2] = ffma2(ee3, u1.x, acc[3][2]);
            acc[3][3] = ffma2(ee3, u1.y, acc[3][3]);
        }
    }

    // ---- epilogue: O = [num|den] -> X = num/den -> out = X @ Wo + bo
    __syncthreads();                 // everyone done reading Es
    float* O = Es;                   // O[h][q][64]
    #pragma unroll
    for (int qi = 0; qi < 4; qi++) {
        #pragma unroll
        for (int dp = 0; dp < 4; dp++) {
            float lo, hi; unpack2(acc[qi][dp], lo, hi);
            int base = (h2 * 32 + q2 + qi) * 64 + d0 + 2 * dp;
            O[base]     = lo;
            O[base + 1] = hi;
        }
    }
    __syncthreads();

    float* X = Ks;                   // X[32][132] (spills into Ws region; both dead)
    for (int i = t; i < 32 * 128; i += 256) {
        int q = i >> 7, j = i & 127;
        int h = j >> 5, d = j & 31;
        float num = O[(h * 32 + q) * 64 + d];
        float den = O[(h * 32 + q) * 64 + 32 + d];
        X[q * 132 + j] = __fdividef(num, den);
    }
    __syncthreads();

    const int qo   = t >> 3;
    const int lat0 = (t & 7) * 4;
    float4 o;
    o.x = bos[lat0]; o.y = bos[lat0 + 1]; o.z = bos[lat0 + 2]; o.w = bos[lat0 + 3];
    #pragma unroll 16
    for (int j = 0; j < 128; j++) {
        float xv = X[qo * 132 + j];
        float4 wv = *(const float4*)&Wos[j * 32 + lat0];
        o.x += xv * wv.x; o.y += xv * wv.y; o.z += xv * wv.z; o.w += xv * wv.w;
    }
    *(float4*)&out[((long)(b * LQ + q0 + qo)) * LATD + lat0] = o;
}

// ---------------- launch ----------------------------------------------------
extern "C" void kernel_launch(void* const* d_in, const int* in_sizes, int n_in,
                              void* d_out, int out_size)
{
    const float* query = (const float*)d_in[0];
    const float* key   = (const float*)d_in[1];
    const float* value = (const float*)d_in[2];
    const int*   mask  = (const int*)  d_in[3];
    const float* Wq    = (const float*)d_in[4];
    const float* bq    = (const float*)d_in[5];
    const float* Wk    = (const float*)d_in[6];
    const float* bk    = (const float*)d_in[7];
    const float* Wo    = (const float*)d_in[8];
    const float* bo    = (const float*)d_in[9];
    float* out = (float*)d_out;
    (void)in_sizes; (void)n_in; (void)out_size;

    cudaFuncSetAttribute(attn_main_kernel,
                         cudaFuncAttributeMaxDynamicSharedMemorySize,
                         SM_FLOATS * (int)sizeof(float));

    // projections
    proj_kernel<<<(BB * LQ) / 64, 256>>>(query, Wq, bq, 0);
    proj_kernel<<<(BB * LK) / 64, 256>>>(key,   Wk, bk, 1);
    // W = [m*v | m]
    wbuild_kernel<<<(BB * LK * 32 + 255) / 256, 256>>>(value, mask);
    // main fused attention + output projection
    dim3 grid(LQ / 32, BB);
    attn_main_kernel<<<grid, 256, SM_FLOATS * (int)sizeof(float)>>>(Wo, bo, out);
}